// round 4
// baseline (speedup 1.0000x reference)
#include <cuda_runtime.h>
#include <cuda_bf16.h>
#include <math_constants.h>
#include <mma.h>

using namespace nvcuda;

#define N_NODES   262144
#define D_IN      512
#define B_GRAPHS  256
#define GATES     2048      // 4*D_IN
#define K_COMB    1024      // combined K (h:512 | r:512)
#define STEPS     6
#define CHUNK     256       // attention chunk (nodes per block)
#define N_CHUNKS  (N_NODES / CHUNK)   // 1024
#define MAX_SLOTS 8         // max chunks a graph can span (~1140/256+1 = 6)

// ----------------- device scratch (no runtime allocation allowed) -----------
__device__ __align__(16) float g_W[GATES * K_COMB];     // combined weights, tf32-rounded
__device__ __align__(16) float g_bias[GATES];           // b_ih + b_hh
__device__ __align__(16) float g_hr[B_GRAPHS * 1024];   // [h | r] = q_star layout
__device__ __align__(16) float g_c[B_GRAPHS * D_IN];
__device__ __align__(16) float g_gates[B_GRAPHS * GATES];
__device__ int   g_off[B_GRAPHS + 1];
// attention partials: per (graph, slot)
__device__ __align__(16) float g_part_r[B_GRAPHS * MAX_SLOTS * D_IN];  // 4 MB
__device__ float g_part_m[B_GRAPHS * MAX_SLOTS];
__device__ float g_part_d[B_GRAPHS * MAX_SLOTS];

// ----------------------------- helpers --------------------------------------
__device__ __forceinline__ float sigm(float v) {
    return 1.0f / (1.0f + __expf(-v));
}
__device__ __forceinline__ float tf32r(float v) {
    unsigned u;
    asm("cvt.rna.tf32.f32 %0, %1;" : "=r"(u) : "f"(v));
    return __uint_as_float(u);
}

// --------------------------- prep kernels -----------------------------------
__global__ void prep_w_kernel(const float* __restrict__ w_ih,
                              const float* __restrict__ w_hh,
                              const float* __restrict__ b_ih,
                              const float* __restrict__ b_hh) {
    int idx = blockIdx.x * blockDim.x + threadIdx.x;   // 0 .. 2048*1024-1
    int n = idx >> 10;
    int k = idx & 1023;
    float v = w_ih[n * 1024 + k];
    if (k < 512) v += w_hh[n * 512 + k];
    g_W[idx] = tf32r(v);
    if (idx < GATES) g_bias[idx] = b_ih[idx] + b_hh[idx];
}

// batch is int32, sorted ascending in [0, B). g_off[t] = lower_bound(batch, t).
__global__ void offsets_kernel(const int* __restrict__ batch) {
    int t = blockIdx.x * blockDim.x + threadIdx.x;
    if (t > B_GRAPHS) return;
    int lo = 0, hi = N_NODES;
    while (lo < hi) {
        int mid = (lo + hi) >> 1;
        if (batch[mid] < t) lo = mid + 1; else hi = mid;
    }
    g_off[t] = lo;
}

// Step 0: q_star = 0, h = 0  ->  gates = bias (identical for every graph)
__global__ void lstm_init_kernel() {
    int b = blockIdx.x;          // 256
    int d = threadIdx.x;         // 512
    float i = sigm(g_bias[d]);
    float g = tanhf(g_bias[1024 + d]);
    float o = sigm(g_bias[1536 + d]);
    float c = i * g;
    g_c[b * D_IN + d]  = c;
    g_hr[b * 1024 + d] = o * tanhf(c);
}

// ----------------- GEMM (tf32 tensor cores): gates = hr @ W^T ----------------
// M=256, N=2048, K=1024. CTA tile 64x64, 8 warps, warp = 1x2 wmma 16x16 tiles.
__global__ void __launch_bounds__(256) gemm_tc_kernel() {
    __shared__ __align__(16) float sA[64][40];
    __shared__ __align__(16) float sB[64][40];

    const int bm = blockIdx.y * 64;        // gridDim.y = 4
    const int bn = blockIdx.x * 64;        // gridDim.x = 32
    const int tid = threadIdx.x;
    const int w   = tid >> 5;              // warp 0..7
    const int mt  = w & 3;                 // M-tile 0..3
    const int ng  = w >> 2;                // N-group 0..1 (two 16-wide tiles)

    wmma::fragment<wmma::accumulator, 16, 16, 8, float> cf[2];
    wmma::fill_fragment(cf[0], 0.0f);
    wmma::fill_fragment(cf[1], 0.0f);

    const int row = tid >> 2;              // 0..63
    const int col = (tid & 3) * 8;         // 0,8,16,24

    const float* Ag = g_hr + (bm + row) * K_COMB + col;
    const float* Bg = g_W  + (bn + row) * K_COMB + col;

    float4 a0 = *(const float4*)(Ag);
    float4 a1 = *(const float4*)(Ag + 4);
    float4 b0 = *(const float4*)(Bg);
    float4 b1 = *(const float4*)(Bg + 4);

    for (int k0 = 0; k0 < K_COMB; k0 += 32) {
        sA[row][col + 0] = tf32r(a0.x); sA[row][col + 1] = tf32r(a0.y);
        sA[row][col + 2] = tf32r(a0.z); sA[row][col + 3] = tf32r(a0.w);
        sA[row][col + 4] = tf32r(a1.x); sA[row][col + 5] = tf32r(a1.y);
        sA[row][col + 6] = tf32r(a1.z); sA[row][col + 7] = tf32r(a1.w);
        sB[row][col + 0] = b0.x; sB[row][col + 1] = b0.y;
        sB[row][col + 2] = b0.z; sB[row][col + 3] = b0.w;
        sB[row][col + 4] = b1.x; sB[row][col + 5] = b1.y;
        sB[row][col + 6] = b1.z; sB[row][col + 7] = b1.w;
        __syncthreads();

        if (k0 + 32 < K_COMB) {
            a0 = *(const float4*)(Ag + k0 + 32);
            a1 = *(const float4*)(Ag + k0 + 36);
            b0 = *(const float4*)(Bg + k0 + 32);
            b1 = *(const float4*)(Bg + k0 + 36);
        }

        #pragma unroll
        for (int kk = 0; kk < 32; kk += 8) {
            wmma::fragment<wmma::matrix_a, 16, 16, 8, wmma::precision::tf32, wmma::row_major> af;
            wmma::load_matrix_sync(af, &sA[mt * 16][kk], 40);
            #pragma unroll
            for (int t = 0; t < 2; t++) {
                wmma::fragment<wmma::matrix_b, 16, 16, 8, wmma::precision::tf32, wmma::col_major> bf;
                wmma::load_matrix_sync(bf, &sB[(ng * 2 + t) * 16][kk], 40);
                wmma::mma_sync(cf[t], af, bf, cf[t]);
            }
        }
        __syncthreads();
    }

    #pragma unroll
    for (int t = 0; t < 2; t++)
        wmma::store_matrix_sync(&g_gates[(bm + mt * 16) * GATES + bn + (ng * 2 + t) * 16],
                                cf[t], GATES, wmma::mem_row_major);
}

// --------------------------- LSTM pointwise (adds bias) ----------------------
__global__ void lstm_pw_kernel() {
    int idx = blockIdx.x * blockDim.x + threadIdx.x;   // 0 .. 131071
    int b = idx >> 9;
    int d = idx & 511;
    const float* gr = g_gates + b * GATES + d;
    float i = sigm(gr[0]    + g_bias[d]);
    float f = sigm(gr[512]  + g_bias[512 + d]);
    float g = tanhf(gr[1024] + g_bias[1024 + d]);
    float o = sigm(gr[1536] + g_bias[1536 + d]);
    float c = f * g_c[idx] + i * g;
    g_c[idx] = c;
    g_hr[b * 1024 + d] = o * tanhf(c);     // q = h into hr[:, :512]
}

// ------------------ attention pass 1: per-chunk partials ---------------------
// 1024 blocks, each owns nodes [chunk*256, chunk*256+256). For every graph
// segment intersecting the range: online softmax -> partial (m, d, num[512])
// written to g_part[b][chunk - first_chunk(b)].
// Register layout (xv/qv): slot j*4+c <-> column 128*j + 4*lane + c.
__global__ void __launch_bounds__(512, 2) attn_chunk_kernel(const float* __restrict__ x) {
    const int chunk = blockIdx.x;
    const int i0 = chunk * CHUNK;
    const int i1 = i0 + CHUNK;
    const int tid  = threadIdx.x;
    const int wid  = tid >> 5;
    const int lane = tid & 31;

    __shared__ float  sm_m[16], sm_d[16], sm_scale[16];
    __shared__ __align__(16) float4 sm_r[16][128];   // 32 KB

    // first graph whose segment contains i0: largest b with off[b] <= i0
    int lo = 0, hi = B_GRAPHS;
    while (lo < hi) {
        int mid = (lo + hi) >> 1;
        if (g_off[mid + 1] <= i0) lo = mid + 1; else hi = mid;
    }
    int b = lo;

    while (b < B_GRAPHS && g_off[b] < i1) {
        const int s0 = max(g_off[b], i0);
        const int s1 = min(g_off[b + 1], i1);
        if (s1 > s0) {
            // q for this graph, same float4 layout as xv
            const float4* q4 = (const float4*)(g_hr + b * 1024);
            float qv[16];
            #pragma unroll
            for (int j = 0; j < 4; j++) {
                float4 v = q4[j * 32 + lane];
                qv[j*4+0] = v.x; qv[j*4+1] = v.y; qv[j*4+2] = v.z; qv[j*4+3] = v.w;
            }

            float m = -CUDART_INF_F, denom = 0.0f;
            float r[16];
            #pragma unroll
            for (int k = 0; k < 16; k++) r[k] = 0.0f;

            for (int n = s0 + wid; n < s1; n += 16) {
                const float4* xr = (const float4*)(x + (size_t)n * D_IN);
                float xv[16];
                #pragma unroll
                for (int j = 0; j < 4; j++) {
                    float4 v = xr[j * 32 + lane];
                    xv[j*4+0] = v.x; xv[j*4+1] = v.y; xv[j*4+2] = v.z; xv[j*4+3] = v.w;
                }
                float p = 0.0f;
                #pragma unroll
                for (int j = 0; j < 16; j++) p = fmaf(xv[j], qv[j], p);
                #pragma unroll
                for (int o = 16; o; o >>= 1) p += __shfl_xor_sync(0xffffffffu, p, o);
                const float e = p;

                const float mn = fmaxf(m, e);
                const float sc = __expf(m - mn);   // first iter: exp(-inf) = 0
                const float wgt = __expf(e - mn);
                denom = fmaf(denom, sc, wgt);
                #pragma unroll
                for (int k = 0; k < 16; k++) r[k] = fmaf(r[k], sc, wgt * xv[k]);
                m = mn;
            }

            if (lane == 0) { sm_m[wid] = m; sm_d[wid] = denom; }
            #pragma unroll
            for (int j = 0; j < 4; j++)
                sm_r[wid][j * 32 + lane] =
                    make_float4(r[j*4+0], r[j*4+1], r[j*4+2], r[j*4+3]);
            __syncthreads();

            float M = -CUDART_INF_F;
            #pragma unroll
            for (int w = 0; w < 16; w++) M = fmaxf(M, sm_m[w]);
            if (tid < 16)
                sm_scale[tid] = (sm_m[tid] == -CUDART_INF_F) ? 0.0f : __expf(sm_m[tid] - M);
            __syncthreads();

            float Dn = 0.0f, num = 0.0f;
            #pragma unroll
            for (int w = 0; w < 16; w++) {
                Dn  += sm_d[w] * sm_scale[w];
                num  = fmaf(((const float*)sm_r[w])[tid], sm_scale[w], num);
            }

            const int slot = chunk - (g_off[b] >> 8);     // CHUNK == 256
            g_part_r[(b * MAX_SLOTS + slot) * D_IN + tid] = num;
            if (tid == 0) {
                g_part_m[b * MAX_SLOTS + slot] = M;
                g_part_d[b * MAX_SLOTS + slot] = Dn;
            }
            __syncthreads();   // smem reused by next segment
        }
        b++;
    }
}

// ------------------ attention pass 2: per-graph merge ------------------------
__global__ void attn_merge_kernel() {
    const int b   = blockIdx.x;      // 256
    const int tid = threadIdx.x;     // 512
    const int o0 = g_off[b], o1 = g_off[b + 1];
    if (o1 <= o0) { g_hr[b * 1024 + 512 + tid] = 0.0f; return; }
    const int j0 = o0 >> 8;
    const int J  = ((o1 - 1) >> 8) - j0 + 1;   // <= MAX_SLOTS

    float M = -CUDART_INF_F;
    for (int j = 0; j < J; j++) M = fmaxf(M, g_part_m[b * MAX_SLOTS + j]);
    float D = 0.0f, acc = 0.0f;
    for (int j = 0; j < J; j++) {
        const float s = __expf(g_part_m[b * MAX_SLOTS + j] - M);
        D   = fmaf(g_part_d[b * MAX_SLOTS + j], s, D);
        acc = fmaf(g_part_r[(b * MAX_SLOTS + j) * D_IN + tid], s, acc);
    }
    g_hr[b * 1024 + 512 + tid] = acc / (D + 1e-16f);
}

// ------------------------------- output --------------------------------------
__global__ void copyout_kernel(float* __restrict__ out) {
    int idx = blockIdx.x * blockDim.x + threadIdx.x;   // 0 .. 262143
    out[idx] = g_hr[idx];
}

// ------------------------------- launch --------------------------------------
extern "C" void kernel_launch(void* const* d_in, const int* in_sizes, int n_in,
                              void* d_out, int out_size) {
    const float* x     = (const float*)d_in[0];
    const int*   batch = (const int*)d_in[1];
    const float* w_ih  = (const float*)d_in[2];
    const float* w_hh  = (const float*)d_in[3];
    const float* b_ih  = (const float*)d_in[4];
    const float* b_hh  = (const float*)d_in[5];
    float* out = (float*)d_out;

    prep_w_kernel<<<(GATES * K_COMB) / 256, 256>>>(w_ih, w_hh, b_ih, b_hh);
    offsets_kernel<<<2, 160>>>(batch);
    lstm_init_kernel<<<B_GRAPHS, 512>>>();

    for (int s = 0; s < STEPS; s++) {
        if (s > 0) {
            gemm_tc_kernel<<<dim3(32, 4), 256>>>();
            lstm_pw_kernel<<<(B_GRAPHS * D_IN) / 512, 512>>>();
        }
        attn_chunk_kernel<<<N_CHUNKS, 512>>>(x);
        attn_merge_kernel<<<B_GRAPHS, 512>>>();
    }
    copyout_kernel<<<(B_GRAPHS * 1024) / 256, 256>>>(out);
}

// round 5
// speedup vs baseline: 1.1768x; 1.1768x over previous
#include <cuda_runtime.h>
#include <cuda_bf16.h>
#include <math_constants.h>
#include <mma.h>

using namespace nvcuda;

#define N_NODES   262144
#define D_IN      512
#define B_GRAPHS  256
#define GATES     2048      // 4*D_IN
#define K_COMB    1024      // combined K (h:512 | r:512)
#define STEPS     6
#define CHUNK     896       // nodes per attention block (293 blocks = 1 wave @ 2 CTA/SM)
#define N_CHUNKS  ((N_NODES + CHUNK - 1) / CHUNK)   // 293
#define MAX_SLOTS 8         // graph spans <= 3 chunks

// ----------------- device scratch (no runtime allocation allowed) -----------
__device__ __align__(16) float g_W[GATES * K_COMB];     // combined weights, tf32-rounded
__device__ __align__(16) float g_bias[GATES];           // b_ih + b_hh
__device__ __align__(16) float g_hr[B_GRAPHS * 1024];   // [h | r] = q_star layout
__device__ __align__(16) float g_c[B_GRAPHS * D_IN];
__device__ __align__(16) float g_gates[B_GRAPHS * GATES];
__device__ int   g_off[B_GRAPHS + 1];
// attention partials: per (graph, slot)
__device__ __align__(16) float g_part_r[B_GRAPHS * MAX_SLOTS * D_IN];  // 4 MB
__device__ float g_part_m[B_GRAPHS * MAX_SLOTS];
__device__ float g_part_d[B_GRAPHS * MAX_SLOTS];

// ----------------------------- helpers --------------------------------------
__device__ __forceinline__ float sigm(float v) {
    return 1.0f / (1.0f + __expf(-v));
}
__device__ __forceinline__ float tf32r(float v) {
    unsigned u;
    asm("cvt.rna.tf32.f32 %0, %1;" : "=r"(u) : "f"(v));
    return __uint_as_float(u);
}

// --------------------------- prep kernels -----------------------------------
__global__ void prep_w_kernel(const float* __restrict__ w_ih,
                              const float* __restrict__ w_hh,
                              const float* __restrict__ b_ih,
                              const float* __restrict__ b_hh) {
    int idx = blockIdx.x * blockDim.x + threadIdx.x;   // 0 .. 2048*1024-1
    int n = idx >> 10;
    int k = idx & 1023;
    float v = w_ih[n * 1024 + k];
    if (k < 512) v += w_hh[n * 512 + k];
    g_W[idx] = tf32r(v);
    if (idx < GATES) g_bias[idx] = b_ih[idx] + b_hh[idx];
}

// batch is int32, sorted ascending in [0, B). g_off[t] = lower_bound(batch, t).
__global__ void offsets_kernel(const int* __restrict__ batch) {
    int t = blockIdx.x * blockDim.x + threadIdx.x;
    if (t > B_GRAPHS) return;
    int lo = 0, hi = N_NODES;
    while (lo < hi) {
        int mid = (lo + hi) >> 1;
        if (batch[mid] < t) lo = mid + 1; else hi = mid;
    }
    g_off[t] = lo;
}

// Step 0: q_star = 0, h = 0  ->  gates = bias (identical for every graph)
__global__ void lstm_init_kernel() {
    int b = blockIdx.x;          // 256
    int d = threadIdx.x;         // 512
    float i = sigm(g_bias[d]);
    float g = tanhf(g_bias[1024 + d]);
    float o = sigm(g_bias[1536 + d]);
    float c = i * g;
    g_c[b * D_IN + d]  = c;
    g_hr[b * 1024 + d] = o * tanhf(c);
}

// ----------------- GEMM (tf32 tensor cores): gates = hr @ W^T ----------------
// M=256, N=2048, K=1024. CTA tile 64x64, 8 warps, warp = 1x2 wmma 16x16 tiles.
__global__ void __launch_bounds__(256) gemm_tc_kernel() {
    __shared__ __align__(16) float sA[64][40];
    __shared__ __align__(16) float sB[64][40];

    const int bm = blockIdx.y * 64;        // gridDim.y = 4
    const int bn = blockIdx.x * 64;        // gridDim.x = 32
    const int tid = threadIdx.x;
    const int w   = tid >> 5;              // warp 0..7
    const int mt  = w & 3;                 // M-tile 0..3
    const int ng  = w >> 2;                // N-group 0..1 (two 16-wide tiles)

    wmma::fragment<wmma::accumulator, 16, 16, 8, float> cf[2];
    wmma::fill_fragment(cf[0], 0.0f);
    wmma::fill_fragment(cf[1], 0.0f);

    const int row = tid >> 2;              // 0..63
    const int col = (tid & 3) * 8;         // 0,8,16,24

    const float* Ag = g_hr + (bm + row) * K_COMB + col;
    const float* Bg = g_W  + (bn + row) * K_COMB + col;

    float4 a0 = *(const float4*)(Ag);
    float4 a1 = *(const float4*)(Ag + 4);
    float4 b0 = *(const float4*)(Bg);
    float4 b1 = *(const float4*)(Bg + 4);

    for (int k0 = 0; k0 < K_COMB; k0 += 32) {
        sA[row][col + 0] = tf32r(a0.x); sA[row][col + 1] = tf32r(a0.y);
        sA[row][col + 2] = tf32r(a0.z); sA[row][col + 3] = tf32r(a0.w);
        sA[row][col + 4] = tf32r(a1.x); sA[row][col + 5] = tf32r(a1.y);
        sA[row][col + 6] = tf32r(a1.z); sA[row][col + 7] = tf32r(a1.w);
        sB[row][col + 0] = b0.x; sB[row][col + 1] = b0.y;
        sB[row][col + 2] = b0.z; sB[row][col + 3] = b0.w;
        sB[row][col + 4] = b1.x; sB[row][col + 5] = b1.y;
        sB[row][col + 6] = b1.z; sB[row][col + 7] = b1.w;
        __syncthreads();

        if (k0 + 32 < K_COMB) {
            a0 = *(const float4*)(Ag + k0 + 32);
            a1 = *(const float4*)(Ag + k0 + 36);
            b0 = *(const float4*)(Bg + k0 + 32);
            b1 = *(const float4*)(Bg + k0 + 36);
        }

        #pragma unroll
        for (int kk = 0; kk < 32; kk += 8) {
            wmma::fragment<wmma::matrix_a, 16, 16, 8, wmma::precision::tf32, wmma::row_major> af;
            wmma::load_matrix_sync(af, &sA[mt * 16][kk], 40);
            #pragma unroll
            for (int t = 0; t < 2; t++) {
                wmma::fragment<wmma::matrix_b, 16, 16, 8, wmma::precision::tf32, wmma::col_major> bf;
                wmma::load_matrix_sync(bf, &sB[(ng * 2 + t) * 16][kk], 40);
                wmma::mma_sync(cf[t], af, bf, cf[t]);
            }
        }
        __syncthreads();
    }

    #pragma unroll
    for (int t = 0; t < 2; t++)
        wmma::store_matrix_sync(&g_gates[(bm + mt * 16) * GATES + bn + (ng * 2 + t) * 16],
                                cf[t], GATES, wmma::mem_row_major);
}

// --------------------------- LSTM pointwise (adds bias) ----------------------
__global__ void lstm_pw_kernel() {
    int idx = blockIdx.x * blockDim.x + threadIdx.x;   // 0 .. 131071
    int b = idx >> 9;
    int d = idx & 511;
    const float* gr = g_gates + b * GATES + d;
    float i = sigm(gr[0]    + g_bias[d]);
    float f = sigm(gr[512]  + g_bias[512 + d]);
    float g = tanhf(gr[1024] + g_bias[1024 + d]);
    float o = sigm(gr[1536] + g_bias[1536 + d]);
    float c = f * g_c[idx] + i * g;
    g_c[idx] = c;
    g_hr[b * 1024 + d] = o * tanhf(c);     // q = h into hr[:, :512]
}

// ------------------ attention pass 1: per-chunk partials ---------------------
// 293 blocks (one full wave @ 2 CTA/SM), each owns nodes
// [chunk*CHUNK, min((chunk+1)*CHUNK, N)). For every graph segment intersecting
// the range: online softmax -> partial (m, d, num[512]) to g_part[b][slot].
// Register layout (xv/qv): slot j*4+c <-> column 128*j + 4*lane + c.
__global__ void __launch_bounds__(512, 2) attn_chunk_kernel(const float* __restrict__ x) {
    const int chunk = blockIdx.x;
    const int i0 = chunk * CHUNK;
    const int i1 = min(i0 + CHUNK, N_NODES);
    const int tid  = threadIdx.x;
    const int wid  = tid >> 5;
    const int lane = tid & 31;

    __shared__ float  sm_m[16], sm_d[16], sm_scale[16];
    __shared__ __align__(16) float4 sm_r[16][128];   // 32 KB

    // first graph whose segment contains i0: largest b with off[b+1] > i0
    int lo = 0, hi = B_GRAPHS;
    while (lo < hi) {
        int mid = (lo + hi) >> 1;
        if (g_off[mid + 1] <= i0) lo = mid + 1; else hi = mid;
    }
    int b = lo;

    while (b < B_GRAPHS && g_off[b] < i1) {
        const int s0 = max(g_off[b], i0);
        const int s1 = min(g_off[b + 1], i1);
        if (s1 > s0) {
            // q for this graph, same float4 layout as xv
            const float4* q4 = (const float4*)(g_hr + b * 1024);
            float qv[16];
            #pragma unroll
            for (int j = 0; j < 4; j++) {
                float4 v = q4[j * 32 + lane];
                qv[j*4+0] = v.x; qv[j*4+1] = v.y; qv[j*4+2] = v.z; qv[j*4+3] = v.w;
            }

            float m = -CUDART_INF_F, denom = 0.0f;
            float r[16];
            #pragma unroll
            for (int k = 0; k < 16; k++) r[k] = 0.0f;

            for (int n = s0 + wid; n < s1; n += 16) {
                const float4* xr = (const float4*)(x + (size_t)n * D_IN);
                float xv[16];
                #pragma unroll
                for (int j = 0; j < 4; j++) {
                    float4 v = __ldcs(xr + j * 32 + lane);   // stream, evict-first
                    xv[j*4+0] = v.x; xv[j*4+1] = v.y; xv[j*4+2] = v.z; xv[j*4+3] = v.w;
                }
                float p = 0.0f;
                #pragma unroll
                for (int j = 0; j < 16; j++) p = fmaf(xv[j], qv[j], p);
                #pragma unroll
                for (int o = 16; o; o >>= 1) p += __shfl_xor_sync(0xffffffffu, p, o);
                const float e = p;

                const float mn = fmaxf(m, e);
                const float sc = __expf(m - mn);   // first iter: exp(-inf) = 0
                const float wgt = __expf(e - mn);
                denom = fmaf(denom, sc, wgt);
                #pragma unroll
                for (int k = 0; k < 16; k++) r[k] = fmaf(r[k], sc, wgt * xv[k]);
                m = mn;
            }

            if (lane == 0) { sm_m[wid] = m; sm_d[wid] = denom; }
            #pragma unroll
            for (int j = 0; j < 4; j++)
                sm_r[wid][j * 32 + lane] =
                    make_float4(r[j*4+0], r[j*4+1], r[j*4+2], r[j*4+3]);
            __syncthreads();

            float M = -CUDART_INF_F;
            #pragma unroll
            for (int w = 0; w < 16; w++) M = fmaxf(M, sm_m[w]);
            if (tid < 16)
                sm_scale[tid] = (sm_m[tid] == -CUDART_INF_F) ? 0.0f : __expf(sm_m[tid] - M);
            __syncthreads();

            float Dn = 0.0f, num = 0.0f;
            #pragma unroll
            for (int w = 0; w < 16; w++) {
                Dn  += sm_d[w] * sm_scale[w];
                num  = fmaf(((const float*)sm_r[w])[tid], sm_scale[w], num);
            }

            const int slot = chunk - g_off[b] / CHUNK;
            g_part_r[(b * MAX_SLOTS + slot) * D_IN + tid] = num;
            if (tid == 0) {
                g_part_m[b * MAX_SLOTS + slot] = M;
                g_part_d[b * MAX_SLOTS + slot] = Dn;
            }
            __syncthreads();   // smem reused by next segment
        }
        b++;
    }
}

// ------------------ attention pass 2: per-graph merge ------------------------
__global__ void attn_merge_kernel() {
    const int b   = blockIdx.x;      // 256
    const int tid = threadIdx.x;     // 512
    const int o0 = g_off[b], o1 = g_off[b + 1];
    if (o1 <= o0) { g_hr[b * 1024 + 512 + tid] = 0.0f; return; }
    const int J = (o1 - 1) / CHUNK - o0 / CHUNK + 1;   // <= MAX_SLOTS

    float M = -CUDART_INF_F;
    for (int j = 0; j < J; j++) M = fmaxf(M, g_part_m[b * MAX_SLOTS + j]);
    float D = 0.0f, acc = 0.0f;
    for (int j = 0; j < J; j++) {
        const float s = __expf(g_part_m[b * MAX_SLOTS + j] - M);
        D   = fmaf(g_part_d[b * MAX_SLOTS + j], s, D);
        acc = fmaf(g_part_r[(b * MAX_SLOTS + j) * D_IN + tid], s, acc);
    }
    g_hr[b * 1024 + 512 + tid] = acc / (D + 1e-16f);
}

// ------------------------------- output --------------------------------------
__global__ void copyout_kernel(float* __restrict__ out) {
    int idx = blockIdx.x * blockDim.x + threadIdx.x;   // 0 .. 262143
    out[idx] = g_hr[idx];
}

// ------------------------------- launch --------------------------------------
extern "C" void kernel_launch(void* const* d_in, const int* in_sizes, int n_in,
                              void* d_out, int out_size) {
    const float* x     = (const float*)d_in[0];
    const int*   batch = (const int*)d_in[1];
    const float* w_ih  = (const float*)d_in[2];
    const float* w_hh  = (const float*)d_in[3];
    const float* b_ih  = (const float*)d_in[4];
    const float* b_hh  = (const float*)d_in[5];
    float* out = (float*)d_out;

    prep_w_kernel<<<(GATES * K_COMB) / 256, 256>>>(w_ih, w_hh, b_ih, b_hh);
    offsets_kernel<<<2, 160>>>(batch);
    lstm_init_kernel<<<B_GRAPHS, 512>>>();

    for (int s = 0; s < STEPS; s++) {
        if (s > 0) {
            gemm_tc_kernel<<<dim3(32, 4), 256>>>();
            lstm_pw_kernel<<<(B_GRAPHS * D_IN) / 512, 512>>>();
        }
        attn_chunk_kernel<<<N_CHUNKS, 512>>>(x);
        attn_merge_kernel<<<B_GRAPHS, 512>>>();
    }
    copyout_kernel<<<(B_GRAPHS * 1024) / 256, 256>>>(out);
}